// round 16
// baseline (speedup 1.0000x reference)
#include <cuda_runtime.h>
#include <cuda_bf16.h>
#include <cuda_fp16.h>
#include <math.h>
#include <stdint.h>

#define BATCH   2
#define SEQ     2048
#define DMODEL  2048
#define NHEADS  16
#define DHEAD   128
#define NTOK    (BATCH * SEQ)      // 4096

// ---------------- scratch (device globals; no allocation allowed) ----------
__device__ __align__(16) __half g_r[(size_t)NTOK * DMODEL];        // residual fp16
__device__ __align__(16) __half g_wq[(size_t)NHEADS * DMODEL * DHEAD];
__device__ __align__(16) __half g_wk[(size_t)NHEADS * DMODEL * DHEAD];
__device__ __align__(16) __half g_wv[(size_t)NHEADS * DMODEL * DHEAD];
__device__ __align__(16) __half g_wo[(size_t)DMODEL * DMODEL];
// attention operands [b][h][s][d]: all single fp16
__device__ __align__(16) __half g_q[(size_t)BATCH * NHEADS * SEQ * DHEAD];
__device__ __align__(16) __half g_k[(size_t)BATCH * NHEADS * SEQ * DHEAD];
__device__ __align__(16) __half g_v[(size_t)BATCH * NHEADS * SEQ * DHEAD];
// attention output: single fp16 [b][s][h][d]
__device__ __align__(16) __half g_z[(size_t)BATCH * SEQ * NHEADS * DHEAD];

// ========================= helpers =========================================
__device__ __forceinline__ void ldsm_x4(uint32_t r[4], uint32_t addr) {
    asm volatile("ldmatrix.sync.aligned.m8n8.x4.shared.b16 {%0,%1,%2,%3}, [%4];"
                 : "=r"(r[0]), "=r"(r[1]), "=r"(r[2]), "=r"(r[3]) : "r"(addr));
}
__device__ __forceinline__ void ldsm_x4_t(uint32_t r[4], uint32_t addr) {
    asm volatile("ldmatrix.sync.aligned.m8n8.x4.trans.shared.b16 {%0,%1,%2,%3}, [%4];"
                 : "=r"(r[0]), "=r"(r[1]), "=r"(r[2]), "=r"(r[3]) : "r"(addr));
}
__device__ __forceinline__ void mma_f16(float c[4], const uint32_t a[4],
                                        uint32_t b0, uint32_t b1) {
    asm volatile("mma.sync.aligned.m16n8k16.row.col.f32.f16.f16.f32 "
                 "{%0,%1,%2,%3}, {%4,%5,%6,%7}, {%8,%9}, {%0,%1,%2,%3};"
                 : "+f"(c[0]), "+f"(c[1]), "+f"(c[2]), "+f"(c[3])
                 : "r"(a[0]), "r"(a[1]), "r"(a[2]), "r"(a[3]), "r"(b0), "r"(b1));
}
__device__ __forceinline__ uint32_t smem_to_u32(const void* p) {
    uint32_t a;
    asm("{ .reg .u64 t; cvta.to.shared.u64 t, %1; cvt.u32.u64 %0, t; }"
        : "=r"(a) : "l"(p));
    return a;
}
__device__ __forceinline__ uint32_t pack2h(__half lo, __half hi) {
    return (uint32_t)__half_as_ushort(lo) | ((uint32_t)__half_as_ushort(hi) << 16);
}
__device__ __forceinline__ void cp_async16(uint32_t dst, const void* src) {
    asm volatile("cp.async.cg.shared.global [%0], [%1], 16;" :: "r"(dst), "l"(src));
}
__device__ __forceinline__ void cp_commit() {
    asm volatile("cp.async.commit_group;" ::: "memory");
}
__device__ __forceinline__ void cp_wait0() {
    asm volatile("cp.async.wait_group 0;" ::: "memory");
}
__device__ __forceinline__ void cp_wait1() {
    asm volatile("cp.async.wait_group 1;" ::: "memory");
}

// ===================== conversion pre-pass (single launch) =================
__global__ __launch_bounds__(256) void convert_all(
    const float* __restrict__ resid,
    const float* __restrict__ WQ, const float* __restrict__ WK,
    const float* __restrict__ WV, const float* __restrict__ WO,
    float* __restrict__ out_resid)
{
    const int which = blockIdx.y;
    int i = blockIdx.x * 256 + threadIdx.x;
    const float* src; __half* dst; int n4;
    switch (which) {
        case 0: src = resid; dst = g_r;  n4 = NTOK * DMODEL / 4; break;
        case 1: src = WQ;    dst = g_wq; n4 = NHEADS * DMODEL * DHEAD / 4; break;
        case 2: src = WK;    dst = g_wk; n4 = NHEADS * DMODEL * DHEAD / 4; break;
        case 3: src = WV;    dst = g_wv; n4 = NHEADS * DMODEL * DHEAD / 4; break;
        default:src = WO;    dst = g_wo; n4 = DMODEL * DMODEL / 4; break;
    }
    if (i >= n4) return;
    float4 v = reinterpret_cast<const float4*>(src)[i];
    reinterpret_cast<uint2*>(dst)[i] =
        make_uint2(pack2h(__float2half(v.x), __float2half(v.y)),
                   pack2h(__float2half(v.z), __float2half(v.w)));
    if (which == 0)
        reinterpret_cast<float4*>(out_resid)[i] = v;   // tuple element 0
}

// ===================== single-pass fp16 GEMM, KT=64 ========================
#define KT1    64
#define STG1   32768
#define SM_GEMM1 (2 * STG1)

__device__ __forceinline__ void gemm1_load_stage(
    uint32_t base, const __half* A, int lda,
    const __half* B, int ldb, int k0, int tid)
{
    #pragma unroll
    for (int it = 0; it < 4; it++) {             // A: 1024 chunks
        int idx = tid + it * 256;
        int m  = idx >> 3;
        int c8 = idx & 7;
        uint32_t d = base + (uint32_t)(m * 128 + ((c8 ^ (m & 7)) << 4));
        cp_async16(d, A + (size_t)m * lda + k0 + c8 * 8);
    }
    #pragma unroll
    for (int it = 0; it < 4; it++) {             // B: 1024 chunks
        int idx = tid + it * 256;
        int k  = idx >> 4;                       // 0..63
        int c8 = idx & 15;
        uint32_t d = base + 16384 + (uint32_t)(k * 256 + ((c8 ^ (k & 7)) << 4));
        cp_async16(d, B + (size_t)(k0 + k) * ldb + c8 * 8);
    }
}

__device__ __forceinline__ void gemm1_compute_stage(
    uint32_t base, int lane, int wm, int wn, float acc[4][4][4])
{
    #pragma unroll
    for (int k16 = 0; k16 < 4; k16++) {
        uint32_t bh[4][2];
        #pragma unroll
        for (int nf = 0; nf < 2; nf++) {
            int kk = k16 * 16 + (lane & 15);
            int nn = wn + nf * 16 + ((lane >> 4) << 3);
            uint32_t off = (uint32_t)(kk * 256 + (((nn >> 3) ^ (kk & 7)) << 4));
            uint32_t r[4];
            ldsm_x4_t(r, base + 16384 + off);
            bh[nf * 2][0] = r[0]; bh[nf * 2][1] = r[1];
            bh[nf * 2 + 1][0] = r[2]; bh[nf * 2 + 1][1] = r[3];
        }
        #pragma unroll
        for (int mi = 0; mi < 4; mi++) {
            int mm = wm + mi * 16 + (lane & 15);
            int c8 = k16 * 2 + (lane >> 4);      // 0..7
            uint32_t off = (uint32_t)(mm * 128 + ((c8 ^ (mm & 7)) << 4));
            uint32_t ah[4];
            ldsm_x4(ah, base + off);
            #pragma unroll
            for (int ni = 0; ni < 4; ni++)
                mma_f16(acc[mi][ni], ah, bh[ni][0], bh[ni][1]);
        }
    }
}

__device__ __forceinline__ void gemm1_mainloop(
    const __half* __restrict__ A, int lda,
    const __half* __restrict__ B, int ldb,
    char* smem, float acc[4][4][4])
{
    const int tid  = threadIdx.x;
    const int lane = tid & 31;
    const int wid  = tid >> 5;
    const int wm   = (wid >> 2) * 64;
    const int wn   = (wid & 3) * 32;
    const uint32_t sb = smem_to_u32(smem);
    const int NIT = DMODEL / KT1;                // 32

    gemm1_load_stage(sb, A, lda, B, ldb, 0, tid);
    cp_commit();

    for (int i = 0; i < NIT; i++) {
        if (i + 1 < NIT) {
            gemm1_load_stage(sb + ((i + 1) & 1) * STG1, A, lda, B, ldb,
                             (i + 1) * KT1, tid);
            cp_commit();
            cp_wait1();
        } else {
            cp_wait0();
        }
        __syncthreads();
        gemm1_compute_stage(sb + (i & 1) * STG1, lane, wm, wn, acc);
        __syncthreads();
    }
}

// ----------------------- QKV projection (single-pass fp16) -----------------
__global__ __launch_bounds__(256, 2) void qkv_tc(
    const float* __restrict__ bQ, const float* __restrict__ bK,
    const float* __restrict__ bV)
{
    extern __shared__ char smem[];
    const int i0 = blockIdx.x * 128;
    const int h  = blockIdx.y;
    const int which = blockIdx.z;

    const __half* W   = (which == 0) ? g_wq : (which == 1) ? g_wk : g_wv;
    const float* bias = (which == 0) ? bQ : (which == 1) ? bK : bV;
    __half* dst       = (which == 0) ? g_q : (which == 1) ? g_k : g_v;

    float acc[4][4][4];
    #pragma unroll
    for (int mi = 0; mi < 4; mi++)
        #pragma unroll
        for (int ni = 0; ni < 4; ni++)
            #pragma unroll
            for (int j = 0; j < 4; j++) acc[mi][ni][j] = 0.0f;

    gemm1_mainloop(g_r + (size_t)i0 * DMODEL, DMODEL,
                   W + (size_t)h * DMODEL * DHEAD, DHEAD, smem, acc);

    const int lane = threadIdx.x & 31;
    const int wid  = threadIdx.x >> 5;
    const int wm   = (wid >> 2) * 64;
    const int wn   = (wid & 3) * 32;
    #pragma unroll
    for (int mi = 0; mi < 4; mi++) {
        #pragma unroll
        for (int ni = 0; ni < 4; ni++) {
            int col = wn + ni * 8 + (lane & 3) * 2;
            float b0 = bias[h * DHEAD + col];
            float b1 = bias[h * DHEAD + col + 1];
            #pragma unroll
            for (int half = 0; half < 2; half++) {
                int i = i0 + wm + mi * 16 + (lane >> 2) + half * 8;
                int bb = i >> 11, s = i & 2047;
                size_t base = (((size_t)bb * NHEADS + h) * SEQ + s) * DHEAD + col;
                *reinterpret_cast<uint32_t*>(&dst[base]) =
                    pack2h(__float2half(acc[mi][ni][half * 2] + b0),
                           __float2half(acc[mi][ni][half * 2 + 1] + b1));
            }
        }
    }
}

// ----------------------- Output projection (single-pass fp16) --------------
__global__ __launch_bounds__(256, 2) void o_tc(
    const float* __restrict__ bO, float* __restrict__ out)
{
    extern __shared__ char smem[];
    const int i0 = blockIdx.x * 128;
    const int j0 = blockIdx.y * 128;

    float acc[4][4][4];
    #pragma unroll
    for (int mi = 0; mi < 4; mi++)
        #pragma unroll
        for (int ni = 0; ni < 4; ni++)
            #pragma unroll
            for (int j = 0; j < 4; j++) acc[mi][ni][j] = 0.0f;

    gemm1_mainloop(g_z + (size_t)i0 * DMODEL, DMODEL, g_wo + j0, DMODEL, smem, acc);

    const int lane = threadIdx.x & 31;
    const int wid  = threadIdx.x >> 5;
    const int wm   = (wid >> 2) * 64;
    const int wn   = (wid & 3) * 32;
    #pragma unroll
    for (int mi = 0; mi < 4; mi++) {
        #pragma unroll
        for (int ni = 0; ni < 4; ni++) {
            int col = j0 + wn + ni * 8 + (lane & 3) * 2;
            float b0 = bO[col], b1 = bO[col + 1];
            #pragma unroll
            for (int half = 0; half < 2; half++) {
                int i = i0 + wm + mi * 16 + (lane >> 2) + half * 8;
                float2 v = make_float2(acc[mi][ni][half * 2] + b0,
                                       acc[mi][ni][half * 2 + 1] + b1);
                *reinterpret_cast<float2*>(out + (size_t)i * DMODEL + col) = v;
            }
        }
    }
}

// ---------------------------------------------------------------------------
// Causal flash attention: single-pass fp16, BK2=128, 1 CTA/SM (R14 config),
// 1D grid with global LPT (heaviest q-tiles dispatched first).
// Stage (64KB): K @0 (32KB), V @32768. 2 stages = 128KB.
// ---------------------------------------------------------------------------
#define BQ2 128
#define BK2 128
#define ATSTG 65536
#define AT_SMEM (2 * ATSTG)
#define NQT (SEQ / BQ2)          // 16 q-tiles

__device__ __forceinline__ void attn_load_kv(
    uint32_t base, const __half* Kg, const __half* Vg, int k0, int tid)
{
    #pragma unroll
    for (int it = 0; it < 8; it++) {
        int idx = tid + it * 256;                // 0..2047
        int r  = idx >> 4;                       // 0..127
        int c8 = idx & 15;
        uint32_t d = (uint32_t)(r * 256 + ((c8 ^ (r & 7)) << 4));
        size_t so = (size_t)(k0 + r) * DHEAD + c8 * 8;
        cp_async16(base + d,         Kg + so);
        cp_async16(base + 32768 + d, Vg + so);
    }
}

__global__ __launch_bounds__(256, 1) void attn_tc()
{
    extern __shared__ char smem[];
    const uint32_t sb = smem_to_u32(smem);
    const int tid  = threadIdx.x;
    const int lane = tid & 31;
    const int w    = tid >> 5;
    // global LPT: first 32 blocks are qi=15 (heaviest), next 32 qi=14, ...
    const int l  = blockIdx.x;                   // 0..511
    const int qi = NQT - 1 - (l >> 5);
    const int hb = l & 31;
    const int h  = hb & 15;
    const int b  = hb >> 4;
    const int q0 = qi * BQ2;

    const size_t head_off = ((size_t)b * NHEADS + h) * SEQ * DHEAD;
    const __half* Qg = g_q + head_off + (size_t)q0 * DHEAD;
    const __half* Kg = g_k + head_off;
    const __half* Vg = g_v + head_off;

    const int NIT = qi + 1;

    // ---- Q prologue (single fp16) into stage-0 K area
    #pragma unroll
    for (int it = 0; it < 8; it++) {
        int idx = tid + it * 256;
        int m  = idx >> 4;
        int c8 = idx & 15;
        uint32_t d = (uint32_t)(m * 256 + ((c8 ^ (m & 7)) << 4));
        cp_async16(sb + d, Qg + (size_t)m * DHEAD + c8 * 8);
    }
    cp_commit();
    cp_wait0();
    __syncthreads();

    uint32_t qh[8][4];
    #pragma unroll
    for (int t = 0; t < 8; t++) {
        int row = w * 16 + (lane & 15);
        int col = t * 16 + ((lane >> 4) << 3);
        uint32_t off = (uint32_t)(row * 256 + (((col >> 3) ^ (row & 7)) << 4));
        ldsm_x4(qh[t], sb + off);
    }
    __syncthreads();

    attn_load_kv(sb, Kg, Vg, 0, tid);
    cp_commit();

    float O[16][4];
    #pragma unroll
    for (int nf = 0; nf < 16; nf++)
        #pragma unroll
        for (int j = 0; j < 4; j++) O[nf][j] = 0.0f;
    float m0 = -INFINITY, m1 = -INFINITY, l0 = 0.0f, l1 = 0.0f;

    const float sc_scale = 0.08838834764831843f;
    const int rbase = q0 + w * 16;

    for (int i = 0; i < NIT; i++) {
        const int k0 = i * BK2;
        if (i + 1 < NIT) {
            attn_load_kv(sb + ((i + 1) & 1) * ATSTG, Kg, Vg, (i + 1) * BK2, tid);
            cp_commit();
            cp_wait1();
        } else {
            cp_wait0();
        }
        __syncthreads();
        const uint32_t base = sb + (i & 1) * ATSTG;

        // ---- S = Q K^T (fp16 single-pass), 128 cols -> 16 n-frags
        float sf[16][4];
        #pragma unroll
        for (int nf = 0; nf < 16; nf++)
            #pragma unroll
            for (int j = 0; j < 4; j++) sf[nf][j] = 0.0f;

        #pragma unroll
        for (int t = 0; t < 8; t++) {
            #pragma unroll
            for (int nb = 0; nb < 8; nb++) {
                int row = nb * 16 + (lane & 15);
                int col = t * 16 + ((lane >> 4) << 3);
                uint32_t off = (uint32_t)(row * 256 + (((col >> 3) ^ (row & 7)) << 4));
                uint32_t kh[4];
                ldsm_x4(kh, base + off);
                mma_f16(sf[2 * nb],     qh[t], kh[0], kh[2]);
                mma_f16(sf[2 * nb + 1], qh[t], kh[1], kh[3]);
            }
        }

        // ---- scale + causal mask (diagonal tile only)
        const bool need_mask = (k0 + BK2 - 1) > (rbase);
        #pragma unroll
        for (int nf = 0; nf < 16; nf++)
            #pragma unroll
            for (int j = 0; j < 4; j++) {
                float s = sf[nf][j] * sc_scale;
                if (need_mask) {
                    int col = k0 + nf * 8 + (lane & 3) * 2 + (j & 1);
                    int row = rbase + (lane >> 2) + (j >> 1) * 8;
                    if (col > row) s = -INFINITY;
                }
                sf[nf][j] = s;
            }

        // ---- online softmax
        float mx0 = -INFINITY, mx1 = -INFINITY;
        #pragma unroll
        for (int nf = 0; nf < 16; nf++) {
            mx0 = fmaxf(mx0, fmaxf(sf[nf][0], sf[nf][1]));
            mx1 = fmaxf(mx1, fmaxf(sf[nf][2], sf[nf][3]));
        }
        mx0 = fmaxf(mx0, __shfl_xor_sync(0xffffffffu, mx0, 1));
        mx0 = fmaxf(mx0, __shfl_xor_sync(0xffffffffu, mx0, 2));
        mx1 = fmaxf(mx1, __shfl_xor_sync(0xffffffffu, mx1, 1));
        mx1 = fmaxf(mx1, __shfl_xor_sync(0xffffffffu, mx1, 2));

        float mn0 = fmaxf(m0, mx0), mn1 = fmaxf(m1, mx1);
        float cr0 = __expf(m0 - mn0), cr1 = __expf(m1 - mn1);

        float sum0 = 0.0f, sum1 = 0.0f;
        #pragma unroll
        for (int nf = 0; nf < 16; nf++) {
            float p0 = __expf(sf[nf][0] - mn0);
            float p1 = __expf(sf[nf][1] - mn0);
            float p2 = __expf(sf[nf][2] - mn1);
            float p3 = __expf(sf[nf][3] - mn1);
            sf[nf][0] = p0; sf[nf][1] = p1; sf[nf][2] = p2; sf[nf][3] = p3;
            sum0 += p0 + p1; sum1 += p2 + p3;
        }
        sum0 += __shfl_xor_sync(0xffffffffu, sum0, 1);
        sum0 += __shfl_xor_sync(0xffffffffu, sum0, 2);
        sum1 += __shfl_xor_sync(0xffffffffu, sum1, 1);
        sum1 += __shfl_xor_sync(0xffffffffu, sum1, 2);
        l0 = l0 * cr0 + sum0;  l1 = l1 * cr1 + sum1;
        m0 = mn0;  m1 = mn1;

        #pragma unroll
        for (int nf = 0; nf < 16; nf++) {
            O[nf][0] *= cr0; O[nf][1] *= cr0;
            O[nf][2] *= cr1; O[nf][3] *= cr1;
        }

        // ---- P -> A frags (fp16, single); 8 k-blocks of 16
        uint32_t pa[8][4];
        #pragma unroll
        for (int kb = 0; kb < 8; kb++) {
            #pragma unroll
            for (int half = 0; half < 2; half++) {
                #pragma unroll
                for (int rr = 0; rr < 2; rr++) {
                    float f0 = sf[2 * kb + half][rr * 2];
                    float f1 = sf[2 * kb + half][rr * 2 + 1];
                    pa[kb][half * 2 + rr] = pack2h(__float2half(f0), __float2half(f1));
                }
            }
        }

        // ---- O += P V (fp16 single-pass)
        #pragma unroll
        for (int kb = 0; kb < 8; kb++) {
            #pragma unroll
            for (int nf2 = 0; nf2 < 8; nf2++) {
                int kk = kb * 16 + (lane & 15);
                int nn = nf2 * 16 + ((lane >> 4) << 3);
                uint32_t off = (uint32_t)(kk * 256 + (((nn >> 3) ^ (kk & 7)) << 4));
                uint32_t vh[4];
                ldsm_x4_t(vh, base + 32768 + off);
                mma_f16(O[2 * nf2],     pa[kb], vh[0], vh[1]);
                mma_f16(O[2 * nf2 + 1], pa[kb], vh[2], vh[3]);
            }
        }
        __syncthreads();
    }

    // ---- normalize + write z (single fp16) [b][s][h][d]
    float inv0 = 1.0f / l0, inv1 = 1.0f / l1;
    int r0 = rbase + (lane >> 2);
    size_t z0 = (((size_t)b * SEQ + r0) * NHEADS + h) * DHEAD;
    size_t z1 = (((size_t)b * SEQ + r0 + 8) * NHEADS + h) * DHEAD;
    #pragma unroll
    for (int nf = 0; nf < 16; nf++) {
        int col = nf * 8 + (lane & 3) * 2;
        *reinterpret_cast<uint32_t*>(&g_z[z0 + col]) =
            pack2h(__float2half(O[nf][0] * inv0), __float2half(O[nf][1] * inv0));
        *reinterpret_cast<uint32_t*>(&g_z[z1 + col]) =
            pack2h(__float2half(O[nf][2] * inv1), __float2half(O[nf][3] * inv1));
    }
}

// ---------------------------------------------------------------------------
extern "C" void kernel_launch(void* const* d_in, const int* in_sizes, int n_in,
                              void* d_out, int out_size)
{
    (void)in_sizes; (void)n_in; (void)out_size;
    const float* residual = (const float*)d_in[0];
    const float* WQ = (const float*)d_in[2];
    const float* WK = (const float*)d_in[3];
    const float* WV = (const float*)d_in[4];
    const float* WO = (const float*)d_in[5];
    const float* bQ = (const float*)d_in[6];
    const float* bK = (const float*)d_in[7];
    const float* bV = (const float*)d_in[8];
    const float* bO = (const float*)d_in[9];
    float* out = (float*)d_out;

    // fused conversion pre-pass (also writes residual pass-through to out)
    dim3 gc(NTOK * DMODEL / 4 / 256, 5);
    convert_all<<<gc, 256>>>(residual, WQ, WK, WV, WO, out);

    cudaFuncSetAttribute(qkv_tc,  cudaFuncAttributeMaxDynamicSharedMemorySize, SM_GEMM1);
    cudaFuncSetAttribute(o_tc,    cudaFuncAttributeMaxDynamicSharedMemorySize, SM_GEMM1);
    cudaFuncSetAttribute(attn_tc, cudaFuncAttributeMaxDynamicSharedMemorySize, AT_SMEM);

    dim3 g1(NTOK / 128, NHEADS, 3);
    qkv_tc<<<g1, 256, SM_GEMM1>>>(bQ, bK, bV);

    // 1D grid, global LPT order
    attn_tc<<<NQT * NHEADS * BATCH, 256, AT_SMEM>>>();

    dim3 g3(NTOK / 128, DMODEL / 128);
    o_tc<<<g3, 256, SM_GEMM1>>>(bO, out + (size_t)BATCH * SEQ * DMODEL);
}

// round 17
// speedup vs baseline: 1.3995x; 1.3995x over previous
#include <cuda_runtime.h>
#include <cuda_bf16.h>
#include <cuda_fp16.h>
#include <math.h>
#include <stdint.h>

#define BATCH   2
#define SEQ     2048
#define DMODEL  2048
#define NHEADS  16
#define DHEAD   128
#define NTOK    (BATCH * SEQ)      // 4096

// ---------------- scratch (device globals; no allocation allowed) ----------
__device__ __align__(16) __half g_r[(size_t)NTOK * DMODEL];        // residual fp16
__device__ __align__(16) __half g_wq[(size_t)NHEADS * DMODEL * DHEAD];
__device__ __align__(16) __half g_wk[(size_t)NHEADS * DMODEL * DHEAD];
__device__ __align__(16) __half g_wv[(size_t)NHEADS * DMODEL * DHEAD];
__device__ __align__(16) __half g_wo[(size_t)DMODEL * DMODEL];
// attention operands [b][h][s][d]: all single fp16
__device__ __align__(16) __half g_q[(size_t)BATCH * NHEADS * SEQ * DHEAD];
__device__ __align__(16) __half g_k[(size_t)BATCH * NHEADS * SEQ * DHEAD];
__device__ __align__(16) __half g_v[(size_t)BATCH * NHEADS * SEQ * DHEAD];
// attention output: single fp16 [b][s][h][d]
__device__ __align__(16) __half g_z[(size_t)BATCH * SEQ * NHEADS * DHEAD];

// ========================= helpers =========================================
__device__ __forceinline__ void ldsm_x4(uint32_t r[4], uint32_t addr) {
    asm volatile("ldmatrix.sync.aligned.m8n8.x4.shared.b16 {%0,%1,%2,%3}, [%4];"
                 : "=r"(r[0]), "=r"(r[1]), "=r"(r[2]), "=r"(r[3]) : "r"(addr));
}
__device__ __forceinline__ void ldsm_x4_t(uint32_t r[4], uint32_t addr) {
    asm volatile("ldmatrix.sync.aligned.m8n8.x4.trans.shared.b16 {%0,%1,%2,%3}, [%4];"
                 : "=r"(r[0]), "=r"(r[1]), "=r"(r[2]), "=r"(r[3]) : "r"(addr));
}
__device__ __forceinline__ void mma_f16(float c[4], const uint32_t a[4],
                                        uint32_t b0, uint32_t b1) {
    asm volatile("mma.sync.aligned.m16n8k16.row.col.f32.f16.f16.f32 "
                 "{%0,%1,%2,%3}, {%4,%5,%6,%7}, {%8,%9}, {%0,%1,%2,%3};"
                 : "+f"(c[0]), "+f"(c[1]), "+f"(c[2]), "+f"(c[3])
                 : "r"(a[0]), "r"(a[1]), "r"(a[2]), "r"(a[3]), "r"(b0), "r"(b1));
}
__device__ __forceinline__ uint32_t smem_to_u32(const void* p) {
    uint32_t a;
    asm("{ .reg .u64 t; cvta.to.shared.u64 t, %1; cvt.u32.u64 %0, t; }"
        : "=r"(a) : "l"(p));
    return a;
}
__device__ __forceinline__ uint32_t pack2h(__half lo, __half hi) {
    return (uint32_t)__half_as_ushort(lo) | ((uint32_t)__half_as_ushort(hi) << 16);
}
__device__ __forceinline__ void cp_async16(uint32_t dst, const void* src) {
    asm volatile("cp.async.cg.shared.global [%0], [%1], 16;" :: "r"(dst), "l"(src));
}
__device__ __forceinline__ void cp_commit() {
    asm volatile("cp.async.commit_group;" ::: "memory");
}
__device__ __forceinline__ void cp_wait0() {
    asm volatile("cp.async.wait_group 0;" ::: "memory");
}
__device__ __forceinline__ void cp_wait1() {
    asm volatile("cp.async.wait_group 1;" ::: "memory");
}

// ===================== conversion pre-pass (single launch) =================
__global__ __launch_bounds__(256) void convert_all(
    const float* __restrict__ resid,
    const float* __restrict__ WQ, const float* __restrict__ WK,
    const float* __restrict__ WV, const float* __restrict__ WO,
    float* __restrict__ out_resid)
{
    const int which = blockIdx.y;
    int i = blockIdx.x * 256 + threadIdx.x;
    const float* src; __half* dst; int n4;
    switch (which) {
        case 0: src = resid; dst = g_r;  n4 = NTOK * DMODEL / 4; break;
        case 1: src = WQ;    dst = g_wq; n4 = NHEADS * DMODEL * DHEAD / 4; break;
        case 2: src = WK;    dst = g_wk; n4 = NHEADS * DMODEL * DHEAD / 4; break;
        case 3: src = WV;    dst = g_wv; n4 = NHEADS * DMODEL * DHEAD / 4; break;
        default:src = WO;    dst = g_wo; n4 = DMODEL * DMODEL / 4; break;
    }
    if (i >= n4) return;
    float4 v = reinterpret_cast<const float4*>(src)[i];
    reinterpret_cast<uint2*>(dst)[i] =
        make_uint2(pack2h(__float2half(v.x), __float2half(v.y)),
                   pack2h(__float2half(v.z), __float2half(v.w)));
    if (which == 0)
        reinterpret_cast<float4*>(out_resid)[i] = v;   // tuple element 0
}

// ===================== single-pass fp16 GEMM, KT=64 ========================
#define KT1    64
#define STG1   32768
#define SM_GEMM1 (2 * STG1)

__device__ __forceinline__ void gemm1_load_stage(
    uint32_t base, const __half* A, int lda,
    const __half* B, int ldb, int k0, int tid)
{
    #pragma unroll
    for (int it = 0; it < 4; it++) {             // A: 1024 chunks
        int idx = tid + it * 256;
        int m  = idx >> 3;
        int c8 = idx & 7;
        uint32_t d = base + (uint32_t)(m * 128 + ((c8 ^ (m & 7)) << 4));
        cp_async16(d, A + (size_t)m * lda + k0 + c8 * 8);
    }
    #pragma unroll
    for (int it = 0; it < 4; it++) {             // B: 1024 chunks
        int idx = tid + it * 256;
        int k  = idx >> 4;                       // 0..63
        int c8 = idx & 15;
        uint32_t d = base + 16384 + (uint32_t)(k * 256 + ((c8 ^ (k & 7)) << 4));
        cp_async16(d, B + (size_t)(k0 + k) * ldb + c8 * 8);
    }
}

__device__ __forceinline__ void gemm1_compute_stage(
    uint32_t base, int lane, int wm, int wn, float acc[4][4][4])
{
    #pragma unroll
    for (int k16 = 0; k16 < 4; k16++) {
        uint32_t bh[4][2];
        #pragma unroll
        for (int nf = 0; nf < 2; nf++) {
            int kk = k16 * 16 + (lane & 15);
            int nn = wn + nf * 16 + ((lane >> 4) << 3);
            uint32_t off = (uint32_t)(kk * 256 + (((nn >> 3) ^ (kk & 7)) << 4));
            uint32_t r[4];
            ldsm_x4_t(r, base + 16384 + off);
            bh[nf * 2][0] = r[0]; bh[nf * 2][1] = r[1];
            bh[nf * 2 + 1][0] = r[2]; bh[nf * 2 + 1][1] = r[3];
        }
        #pragma unroll
        for (int mi = 0; mi < 4; mi++) {
            int mm = wm + mi * 16 + (lane & 15);
            int c8 = k16 * 2 + (lane >> 4);      // 0..7
            uint32_t off = (uint32_t)(mm * 128 + ((c8 ^ (mm & 7)) << 4));
            uint32_t ah[4];
            ldsm_x4(ah, base + off);
            #pragma unroll
            for (int ni = 0; ni < 4; ni++)
                mma_f16(acc[mi][ni], ah, bh[ni][0], bh[ni][1]);
        }
    }
}

__device__ __forceinline__ void gemm1_mainloop(
    const __half* __restrict__ A, int lda,
    const __half* __restrict__ B, int ldb,
    char* smem, float acc[4][4][4])
{
    const int tid  = threadIdx.x;
    const int lane = tid & 31;
    const int wid  = tid >> 5;
    const int wm   = (wid >> 2) * 64;
    const int wn   = (wid & 3) * 32;
    const uint32_t sb = smem_to_u32(smem);
    const int NIT = DMODEL / KT1;                // 32

    gemm1_load_stage(sb, A, lda, B, ldb, 0, tid);
    cp_commit();

    for (int i = 0; i < NIT; i++) {
        if (i + 1 < NIT) {
            gemm1_load_stage(sb + ((i + 1) & 1) * STG1, A, lda, B, ldb,
                             (i + 1) * KT1, tid);
            cp_commit();
            cp_wait1();
        } else {
            cp_wait0();
        }
        __syncthreads();
        gemm1_compute_stage(sb + (i & 1) * STG1, lane, wm, wn, acc);
        __syncthreads();
    }
}

// ----------------------- QKV projection (single-pass fp16) -----------------
__global__ __launch_bounds__(256, 2) void qkv_tc(
    const float* __restrict__ bQ, const float* __restrict__ bK,
    const float* __restrict__ bV)
{
    extern __shared__ char smem[];
    const int i0 = blockIdx.x * 128;
    const int h  = blockIdx.y;
    const int which = blockIdx.z;

    const __half* W   = (which == 0) ? g_wq : (which == 1) ? g_wk : g_wv;
    const float* bias = (which == 0) ? bQ : (which == 1) ? bK : bV;
    __half* dst       = (which == 0) ? g_q : (which == 1) ? g_k : g_v;

    float acc[4][4][4];
    #pragma unroll
    for (int mi = 0; mi < 4; mi++)
        #pragma unroll
        for (int ni = 0; ni < 4; ni++)
            #pragma unroll
            for (int j = 0; j < 4; j++) acc[mi][ni][j] = 0.0f;

    gemm1_mainloop(g_r + (size_t)i0 * DMODEL, DMODEL,
                   W + (size_t)h * DMODEL * DHEAD, DHEAD, smem, acc);

    const int lane = threadIdx.x & 31;
    const int wid  = threadIdx.x >> 5;
    const int wm   = (wid >> 2) * 64;
    const int wn   = (wid & 3) * 32;
    #pragma unroll
    for (int mi = 0; mi < 4; mi++) {
        #pragma unroll
        for (int ni = 0; ni < 4; ni++) {
            int col = wn + ni * 8 + (lane & 3) * 2;
            float b0 = bias[h * DHEAD + col];
            float b1 = bias[h * DHEAD + col + 1];
            #pragma unroll
            for (int half = 0; half < 2; half++) {
                int i = i0 + wm + mi * 16 + (lane >> 2) + half * 8;
                int bb = i >> 11, s = i & 2047;
                size_t base = (((size_t)bb * NHEADS + h) * SEQ + s) * DHEAD + col;
                *reinterpret_cast<uint32_t*>(&dst[base]) =
                    pack2h(__float2half(acc[mi][ni][half * 2] + b0),
                           __float2half(acc[mi][ni][half * 2 + 1] + b1));
            }
        }
    }
}

// ----------------------- Output projection (single-pass fp16) --------------
__global__ __launch_bounds__(256, 2) void o_tc(
    const float* __restrict__ bO, float* __restrict__ out)
{
    extern __shared__ char smem[];
    const int i0 = blockIdx.x * 128;
    const int j0 = blockIdx.y * 128;

    float acc[4][4][4];
    #pragma unroll
    for (int mi = 0; mi < 4; mi++)
        #pragma unroll
        for (int ni = 0; ni < 4; ni++)
            #pragma unroll
            for (int j = 0; j < 4; j++) acc[mi][ni][j] = 0.0f;

    gemm1_mainloop(g_z + (size_t)i0 * DMODEL, DMODEL, g_wo + j0, DMODEL, smem, acc);

    const int lane = threadIdx.x & 31;
    const int wid  = threadIdx.x >> 5;
    const int wm   = (wid >> 2) * 64;
    const int wn   = (wid & 3) * 32;
    #pragma unroll
    for (int mi = 0; mi < 4; mi++) {
        #pragma unroll
        for (int ni = 0; ni < 4; ni++) {
            int col = j0 + wn + ni * 8 + (lane & 3) * 2;
            float b0 = bO[col], b1 = bO[col + 1];
            #pragma unroll
            for (int half = 0; half < 2; half++) {
                int i = i0 + wm + mi * 16 + (lane >> 2) + half * 8;
                float2 v = make_float2(acc[mi][ni][half * 2] + b0,
                                       acc[mi][ni][half * 2 + 1] + b1);
                *reinterpret_cast<float2*>(out + (size_t)i * DMODEL + col) = v;
            }
        }
    }
}

// ---------------------------------------------------------------------------
// Causal flash attention: single-pass fp16, BK2=128, 1 CTA/SM,
// 3D grid with per-head heavy-first (qi reversed on x). R14 config.
// Stage (64KB): K @0 (32KB), V @32768. 2 stages = 128KB.
// ---------------------------------------------------------------------------
#define BQ2 128
#define BK2 128
#define ATSTG 65536
#define AT_SMEM (2 * ATSTG)

__device__ __forceinline__ void attn_load_kv(
    uint32_t base, const __half* Kg, const __half* Vg, int k0, int tid)
{
    #pragma unroll
    for (int it = 0; it < 8; it++) {
        int idx = tid + it * 256;                // 0..2047
        int r  = idx >> 4;                       // 0..127
        int c8 = idx & 15;
        uint32_t d = (uint32_t)(r * 256 + ((c8 ^ (r & 7)) << 4));
        size_t so = (size_t)(k0 + r) * DHEAD + c8 * 8;
        cp_async16(base + d,         Kg + so);
        cp_async16(base + 32768 + d, Vg + so);
    }
}

__global__ __launch_bounds__(256, 1) void attn_tc()
{
    extern __shared__ char smem[];
    const uint32_t sb = smem_to_u32(smem);
    const int tid  = threadIdx.x;
    const int lane = tid & 31;
    const int w    = tid >> 5;
    const int qi   = gridDim.x - 1 - blockIdx.x;   // heavy tiles launch first
    const int q0   = qi * BQ2;
    const int h    = blockIdx.y;
    const int b    = blockIdx.z;

    const size_t head_off = ((size_t)b * NHEADS + h) * SEQ * DHEAD;
    const __half* Qg = g_q + head_off + (size_t)q0 * DHEAD;
    const __half* Kg = g_k + head_off;
    const __half* Vg = g_v + head_off;

    const int NIT = qi + 1;

    // ---- Q prologue (single fp16) into stage-0 K area
    #pragma unroll
    for (int it = 0; it < 8; it++) {
        int idx = tid + it * 256;
        int m  = idx >> 4;
        int c8 = idx & 15;
        uint32_t d = (uint32_t)(m * 256 + ((c8 ^ (m & 7)) << 4));
        cp_async16(sb + d, Qg + (size_t)m * DHEAD + c8 * 8);
    }
    cp_commit();
    cp_wait0();
    __syncthreads();

    uint32_t qh[8][4];
    #pragma unroll
    for (int t = 0; t < 8; t++) {
        int row = w * 16 + (lane & 15);
        int col = t * 16 + ((lane >> 4) << 3);
        uint32_t off = (uint32_t)(row * 256 + (((col >> 3) ^ (row & 7)) << 4));
        ldsm_x4(qh[t], sb + off);
    }
    __syncthreads();

    attn_load_kv(sb, Kg, Vg, 0, tid);
    cp_commit();

    float O[16][4];
    #pragma unroll
    for (int nf = 0; nf < 16; nf++)
        #pragma unroll
        for (int j = 0; j < 4; j++) O[nf][j] = 0.0f;
    float m0 = -INFINITY, m1 = -INFINITY, l0 = 0.0f, l1 = 0.0f;

    const float sc_scale = 0.08838834764831843f;
    const int rbase = q0 + w * 16;

    for (int i = 0; i < NIT; i++) {
        const int k0 = i * BK2;
        if (i + 1 < NIT) {
            attn_load_kv(sb + ((i + 1) & 1) * ATSTG, Kg, Vg, (i + 1) * BK2, tid);
            cp_commit();
            cp_wait1();
        } else {
            cp_wait0();
        }
        __syncthreads();
        const uint32_t base = sb + (i & 1) * ATSTG;

        // ---- S = Q K^T (fp16 single-pass), 128 cols -> 16 n-frags
        float sf[16][4];
        #pragma unroll
        for (int nf = 0; nf < 16; nf++)
            #pragma unroll
            for (int j = 0; j < 4; j++) sf[nf][j] = 0.0f;

        #pragma unroll
        for (int t = 0; t < 8; t++) {
            #pragma unroll
            for (int nb = 0; nb < 8; nb++) {
                int row = nb * 16 + (lane & 15);
                int col = t * 16 + ((lane >> 4) << 3);
                uint32_t off = (uint32_t)(row * 256 + (((col >> 3) ^ (row & 7)) << 4));
                uint32_t kh[4];
                ldsm_x4(kh, base + off);
                mma_f16(sf[2 * nb],     qh[t], kh[0], kh[2]);
                mma_f16(sf[2 * nb + 1], qh[t], kh[1], kh[3]);
            }
        }

        // ---- scale + causal mask (diagonal tile only)
        const bool need_mask = (k0 + BK2 - 1) > (rbase);
        #pragma unroll
        for (int nf = 0; nf < 16; nf++)
            #pragma unroll
            for (int j = 0; j < 4; j++) {
                float s = sf[nf][j] * sc_scale;
                if (need_mask) {
                    int col = k0 + nf * 8 + (lane & 3) * 2 + (j & 1);
                    int row = rbase + (lane >> 2) + (j >> 1) * 8;
                    if (col > row) s = -INFINITY;
                }
                sf[nf][j] = s;
            }

        // ---- online softmax
        float mx0 = -INFINITY, mx1 = -INFINITY;
        #pragma unroll
        for (int nf = 0; nf < 16; nf++) {
            mx0 = fmaxf(mx0, fmaxf(sf[nf][0], sf[nf][1]));
            mx1 = fmaxf(mx1, fmaxf(sf[nf][2], sf[nf][3]));
        }
        mx0 = fmaxf(mx0, __shfl_xor_sync(0xffffffffu, mx0, 1));
        mx0 = fmaxf(mx0, __shfl_xor_sync(0xffffffffu, mx0, 2));
        mx1 = fmaxf(mx1, __shfl_xor_sync(0xffffffffu, mx1, 1));
        mx1 = fmaxf(mx1, __shfl_xor_sync(0xffffffffu, mx1, 2));

        float mn0 = fmaxf(m0, mx0), mn1 = fmaxf(m1, mx1);
        float cr0 = __expf(m0 - mn0), cr1 = __expf(m1 - mn1);

        float sum0 = 0.0f, sum1 = 0.0f;
        #pragma unroll
        for (int nf = 0; nf < 16; nf++) {
            float p0 = __expf(sf[nf][0] - mn0);
            float p1 = __expf(sf[nf][1] - mn0);
            float p2 = __expf(sf[nf][2] - mn1);
            float p3 = __expf(sf[nf][3] - mn1);
            sf[nf][0] = p0; sf[nf][1] = p1; sf[nf][2] = p2; sf[nf][3] = p3;
            sum0 += p0 + p1; sum1 += p2 + p3;
        }
        sum0 += __shfl_xor_sync(0xffffffffu, sum0, 1);
        sum0 += __shfl_xor_sync(0xffffffffu, sum0, 2);
        sum1 += __shfl_xor_sync(0xffffffffu, sum1, 1);
        sum1 += __shfl_xor_sync(0xffffffffu, sum1, 2);
        l0 = l0 * cr0 + sum0;  l1 = l1 * cr1 + sum1;
        m0 = mn0;  m1 = mn1;

        #pragma unroll
        for (int nf = 0; nf < 16; nf++) {
            O[nf][0] *= cr0; O[nf][1] *= cr0;
            O[nf][2] *= cr1; O[nf][3] *= cr1;
        }

        // ---- P -> A frags (fp16, single); 8 k-blocks of 16
        uint32_t pa[8][4];
        #pragma unroll
        for (int kb = 0; kb < 8; kb++) {
            #pragma unroll
            for (int half = 0; half < 2; half++) {
                #pragma unroll
                for (int rr = 0; rr < 2; rr++) {
                    float f0 = sf[2 * kb + half][rr * 2];
                    float f1 = sf[2 * kb + half][rr * 2 + 1];
                    pa[kb][half * 2 + rr] = pack2h(__float2half(f0), __float2half(f1));
                }
            }
        }

        // ---- O += P V (fp16 single-pass)
        #pragma unroll
        for (int kb = 0; kb < 8; kb++) {
            #pragma unroll
            for (int nf2 = 0; nf2 < 8; nf2++) {
                int kk = kb * 16 + (lane & 15);
                int nn = nf2 * 16 + ((lane >> 4) << 3);
                uint32_t off = (uint32_t)(kk * 256 + (((nn >> 3) ^ (kk & 7)) << 4));
                uint32_t vh[4];
                ldsm_x4_t(vh, base + 32768 + off);
                mma_f16(O[2 * nf2],     pa[kb], vh[0], vh[1]);
                mma_f16(O[2 * nf2 + 1], pa[kb], vh[2], vh[3]);
            }
        }
        __syncthreads();
    }

    // ---- normalize + write z (single fp16) [b][s][h][d]
    float inv0 = 1.0f / l0, inv1 = 1.0f / l1;
    int r0 = rbase + (lane >> 2);
    size_t z0 = (((size_t)b * SEQ + r0) * NHEADS + h) * DHEAD;
    size_t z1 = (((size_t)b * SEQ + r0 + 8) * NHEADS + h) * DHEAD;
    #pragma unroll
    for (int nf = 0; nf < 16; nf++) {
        int col = nf * 8 + (lane & 3) * 2;
        *reinterpret_cast<uint32_t*>(&g_z[z0 + col]) =
            pack2h(__float2half(O[nf][0] * inv0), __float2half(O[nf][1] * inv0));
        *reinterpret_cast<uint32_t*>(&g_z[z1 + col]) =
            pack2h(__float2half(O[nf][2] * inv1), __float2half(O[nf][3] * inv1));
    }
}

// ---------------------------------------------------------------------------
extern "C" void kernel_launch(void* const* d_in, const int* in_sizes, int n_in,
                              void* d_out, int out_size)
{
    (void)in_sizes; (void)n_in; (void)out_size;
    const float* residual = (const float*)d_in[0];
    const float* WQ = (const float*)d_in[2];
    const float* WK = (const float*)d_in[3];
    const float* WV = (const float*)d_in[4];
    const float* WO = (const float*)d_in[5];
    const float* bQ = (const float*)d_in[6];
    const float* bK = (const float*)d_in[7];
    const float* bV = (const float*)d_in[8];
    const float* bO = (const float*)d_in[9];
    float* out = (float*)d_out;

    // fused conversion pre-pass (also writes residual pass-through to out)
    dim3 gc(NTOK * DMODEL / 4 / 256, 5);
    convert_all<<<gc, 256>>>(residual, WQ, WK, WV, WO, out);

    cudaFuncSetAttribute(qkv_tc,  cudaFuncAttributeMaxDynamicSharedMemorySize, SM_GEMM1);
    cudaFuncSetAttribute(o_tc,    cudaFuncAttributeMaxDynamicSharedMemorySize, SM_GEMM1);
    cudaFuncSetAttribute(attn_tc, cudaFuncAttributeMaxDynamicSharedMemorySize, AT_SMEM);

    dim3 g1(NTOK / 128, NHEADS, 3);
    qkv_tc<<<g1, 256, SM_GEMM1>>>(bQ, bK, bV);

    dim3 g2(SEQ / BQ2, NHEADS, BATCH);
    attn_tc<<<g2, 256, AT_SMEM>>>();

    dim3 g3(NTOK / 128, DMODEL / 128);
    o_tc<<<g3, 256, SM_GEMM1>>>(bO, out + (size_t)BATCH * SEQ * DMODEL);
}